// round 13
// baseline (speedup 1.0000x reference)
#include <cuda_runtime.h>
#include <cuda_fp16.h>
#include <math.h>

#define NMAX 50000
#define EMAX 800000
#define HDIM 64

// ---------------- scratch (static __device__, no allocation) ----------------
__device__ float  g_hyp[NMAX * HDIM];
__device__ float  g_h0 [NMAX * HDIM];
__device__ float  g_h1 [NMAX * HDIM];
__device__ __half g_yh [NMAX * HDIM];
__device__ float  g_z  [NMAX * HDIM];
__device__ int    g_rowptr[NMAX + 1];
__device__ int    g_cnt[NMAX];
__device__ int    g_epos[EMAX];
__device__ int    g_adj[EMAX];

__device__ __forceinline__ unsigned smaddr(const void* p) {
    return (unsigned)__cvta_generic_to_shared(p);
}

// ---------------- CSR build ----------------
__global__ void count_kernel(const int* __restrict__ dst, int* cnt, int* pos, int E) {
    int e = blockIdx.x * blockDim.x + threadIdx.x;
    if (e < E) pos[e] = atomicAdd(&cnt[dst[e]], 1);
}

__global__ void scan_kernel(const int* __restrict__ cnt, int* rowptr, int N) {
    __shared__ int s[1024];
    int t = threadIdx.x;
    int chunk = (N + 1023) / 1024;
    int beg = t * chunk;
    int end = min(beg + chunk, N);
    int sum = 0;
    for (int i = beg; i < end; i++) sum += cnt[i];
    s[t] = sum;
    __syncthreads();
    for (int off = 1; off < 1024; off <<= 1) {
        int v = (t >= off) ? s[t - off] : 0;
        __syncthreads();
        s[t] += v;
        __syncthreads();
    }
    int run = s[t] - sum;
    for (int i = beg; i < end; i++) { rowptr[i] = run; run += cnt[i]; }
    if (end == N) rowptr[N] = run;
}

__global__ void fill_kernel(const int* __restrict__ src, const int* __restrict__ dst,
                            const int* __restrict__ rowptr, const int* __restrict__ pos,
                            int* adj, int E) {
    int e = blockIdx.x * blockDim.x + threadIdx.x;
    if (e < E) adj[rowptr[dst[e]] + pos[e]] = src[e];
}

// ------ dual GEMM via HMMA: Yh = A@Wl (fp16 out); Z = A@Wr + b (+hyp) -------
// A:[N,64] fp32, Wl/Wr:[64,64] fp32 k-major. Block: 64 nodes, 256 thr (8 warps).
// Warps 0-3: Y (16 nodes x 64 cols each); warps 4-7: Z.
#define LDA 72   // padded row (halves): 144B stride -> ldmatrix conflict-free
__global__ __launch_bounds__(256)
void gemm_dual_mma(const float* __restrict__ A,
                   const float* __restrict__ Wl, const float* __restrict__ Wr,
                   const float* __restrict__ bias, const float* __restrict__ hyp,
                   __half* __restrict__ Yh, float* __restrict__ Z, int N) {
    __shared__ __half Ah[64 * LDA];
    __shared__ __half Wh[2][64 * LDA];
    const int node0 = blockIdx.x * 64;
    const int tid = threadIdx.x;

    // stage W (both matrices): 8192 elems / 256 thr = 32 each, j contiguous
#pragma unroll
    for (int r = 0; r < 32; r++) {
        int idx = r * 256 + tid;
        int m = idx >> 12;
        int rem = idx & 4095;
        int k = rem >> 6, j = rem & 63;
        float v = m ? __ldg(&Wr[k * 64 + j]) : __ldg(&Wl[k * 64 + j]);
        Wh[m][k * LDA + j] = __float2half_rn(v);
    }
    // stage A: thread t -> node t>>2, 16-col chunk (t&3)
    {
        int node = tid >> 2, c = tid & 3;
        int n = node0 + node;
        __half2 hbuf[8];
        if (n < N) {
            const float4* a4 = (const float4*)(A + (size_t)n * 64 + c * 16);
#pragma unroll
            for (int i = 0; i < 4; i++) {
                float4 v = __ldg(a4 + i);
                hbuf[2 * i]     = __floats2half2_rn(v.x, v.y);
                hbuf[2 * i + 1] = __floats2half2_rn(v.z, v.w);
            }
        } else {
#pragma unroll
            for (int i = 0; i < 8; i++) hbuf[i] = __floats2half2_rn(0.f, 0.f);
        }
        // 16 halves = 32B to Ah[node][c*16..]; row base 144B-aligned, +c*32B -> 16B aligned
        uint4* dstp = (uint4*)&Ah[node * LDA + c * 16];
        dstp[0] = *(const uint4*)&hbuf[0];
        dstp[1] = *(const uint4*)&hbuf[4];
    }
    __syncthreads();

    const int lane = tid & 31;
    const int w = tid >> 5;
    const int sel = w >> 2;            // 0 = Y(Wl), 1 = Z(Wr)
    const int mrow0 = (w & 3) * 16;
    const __half* Ws = Wh[sel];

    float d[8][4];
#pragma unroll
    for (int t = 0; t < 8; t++)
#pragma unroll
        for (int j = 0; j < 4; j++) d[t][j] = 0.f;

#pragma unroll
    for (int kt = 0; kt < 4; kt++) {
        unsigned a0, a1, a2, a3;
        unsigned aaddr = smaddr(&Ah[(mrow0 + (lane & 15)) * LDA + (lane >> 4) * 8 + kt * 16]);
        asm volatile("ldmatrix.sync.aligned.m8n8.x4.shared.b16 {%0,%1,%2,%3}, [%4];"
                     : "=r"(a0), "=r"(a1), "=r"(a2), "=r"(a3) : "r"(aaddr));
#pragma unroll
        for (int t = 0; t < 8; t++) {
            unsigned b0, b1;
            unsigned baddr = smaddr(&Ws[(kt * 16 + (lane & 15)) * LDA + t * 8]);
            asm volatile("ldmatrix.sync.aligned.m8n8.x2.trans.shared.b16 {%0,%1}, [%2];"
                         : "=r"(b0), "=r"(b1) : "r"(baddr));
            asm volatile("mma.sync.aligned.m16n8k16.row.col.f32.f16.f16.f32 "
                         "{%0,%1,%2,%3},{%4,%5,%6,%7},{%8,%9},{%0,%1,%2,%3};"
                         : "+f"(d[t][0]), "+f"(d[t][1]), "+f"(d[t][2]), "+f"(d[t][3])
                         : "r"(a0), "r"(a1), "r"(a2), "r"(a3), "r"(b0), "r"(b1));
        }
    }

    // epilogue: lane -> rows g, g+8 ; cols 2*tg+tile*8
    const int g = lane >> 2, tg = lane & 3;
    const int n1 = node0 + mrow0 + g;
    const int n2 = n1 + 8;
    if (sel == 0) {
#pragma unroll
        for (int t = 0; t < 8; t++) {
            int jc = t * 8 + 2 * tg;
            if (n1 < N) *(__half2*)&Yh[(size_t)n1 * 64 + jc] = __floats2half2_rn(d[t][0], d[t][1]);
            if (n2 < N) *(__half2*)&Yh[(size_t)n2 * 64 + jc] = __floats2half2_rn(d[t][2], d[t][3]);
        }
    } else {
#pragma unroll
        for (int t = 0; t < 8; t++) {
            int jc = t * 8 + 2 * tg;
            float2 b2 = *(const float2*)&bias[jc];
            if (n1 < N) {
                float2 v = make_float2(d[t][0] + b2.x, d[t][1] + b2.y);
                if (hyp) {
                    float2 hv = __ldg((const float2*)&hyp[(size_t)n1 * 64 + jc]);
                    v.x += hv.x; v.y += hv.y;
                }
                *(float2*)&Z[(size_t)n1 * 64 + jc] = v;
            }
            if (n2 < N) {
                float2 v = make_float2(d[t][2] + b2.x, d[t][3] + b2.y);
                if (hyp) {
                    float2 hv = __ldg((const float2*)&hyp[(size_t)n2 * 64 + jc]);
                    v.x += hv.x; v.y += hv.y;
                }
                *(float2*)&Z[(size_t)n2 * 64 + jc] = v;
            }
        }
    }
}

// ------------- fused gather-mean + Z + act: out = act(mean(Yh[src]) + Z) ----
__global__ void agg_epi(const __half* __restrict__ Yh, const float* __restrict__ Z,
                        float* __restrict__ out,
                        const int* __restrict__ rowptr, const int* __restrict__ adj,
                        int N, int relu) {
    int gw = (blockIdx.x * blockDim.x + threadIdx.x) >> 5;
    int lane = threadIdx.x & 31;
    if (gw >= N) return;
    int beg = rowptr[gw];
    int end = rowptr[gw + 1];
    float ax = 0.f, ay = 0.f;
#pragma unroll 4
    for (int e = beg; e < end; e++) {
        int s = __ldg(&adj[e]);
        __half2 hv = __ldg(((const __half2*)(Yh + (size_t)s * HDIM)) + lane);
        float2 v = __half22float2(hv);
        ax += v.x; ay += v.y;
    }
    float inv = 1.f / (float)max(end - beg, 1);
    float2 z = __ldg(((const float2*)(Z + (size_t)gw * HDIM)) + lane);
    float ox = ax * inv + z.x;
    float oy = ay * inv + z.y;
    if (relu) { ox = fmaxf(ox, 0.f); oy = fmaxf(oy, 0.f); }
    ((float2*)(out + (size_t)gw * HDIM))[lane] = make_float2(ox, oy);
}

// ---------------- pos: out = tanh(pos @ W_pos + b), warp-per-node -----------
__global__ __launch_bounds__(256)
void pos_kernel(const float* __restrict__ pos, const float* __restrict__ W,
                const float* __restrict__ b, float* __restrict__ out, int N) {
    __shared__ float Ws[16 * 64];
    __shared__ float bs[64];
    int tid = threadIdx.x;
    for (int i = tid; i < 16 * 64; i += 256) Ws[i] = W[i];
    if (tid < 64) bs[tid] = b[tid];
    __syncthreads();

    int warp = tid >> 5, lane = tid & 31;
    int n = blockIdx.x * 8 + warp;
    if (n >= N) return;

    float pval = (lane < 16) ? __ldg(&pos[(size_t)n * 16 + lane]) : 0.f;
    int j0 = lane * 2;
    float a0 = bs[j0], a1 = bs[j0 + 1];
#pragma unroll
    for (int k = 0; k < 16; k++) {
        float pv = __shfl_sync(0xffffffffu, pval, k);
        float2 w = *(const float2*)&Ws[k * 64 + j0];
        a0 += pv * w.x; a1 += pv * w.y;
    }
    ((float2*)(out + (size_t)n * 64))[lane] = make_float2(tanhf(a0), tanhf(a1));
}

// ---------------- init GEMM: out[N,64] = A@W + b; A:[N,128] -----------------
__global__ void gemm_n64(const float* __restrict__ A0, int K0,
                         const float* __restrict__ W0,
                         const float* __restrict__ bias,
                         float* __restrict__ out, int N, int act) {
    __shared__ float As[128 * 68];
    const int node0 = blockIdx.x * 64;
    const int tid = threadIdx.x;
    const int K = K0;

    for (int i = tid; i < 64 * K; i += 256) {
        int nl = i / K, k = i - nl * K;
        int n = node0 + nl;
        float v = 0.f;
        if (n < N) v = A0[(size_t)n * K0 + k];
        As[k * 68 + nl] = v;
    }
    __syncthreads();

    const int fr = tid & 15;
    const int nr = tid >> 4;
    float acc[4][4];
#pragma unroll
    for (int i = 0; i < 4; i++)
#pragma unroll
        for (int j = 0; j < 4; j++) acc[i][j] = 0.f;

#pragma unroll 4
    for (int k = 0; k < K; k++) {
        float4 av = *(const float4*)&As[k * 68 + nr * 4];
        float4 wv = __ldg((const float4*)&W0[(size_t)k * 64 + fr * 4]);
        float a[4] = {av.x, av.y, av.z, av.w};
        float w[4] = {wv.x, wv.y, wv.z, wv.w};
#pragma unroll
        for (int i = 0; i < 4; i++)
#pragma unroll
            for (int j = 0; j < 4; j++) acc[i][j] += a[i] * w[j];
    }

    float b0 = bias[fr * 4 + 0], b1 = bias[fr * 4 + 1];
    float b2 = bias[fr * 4 + 2], b3 = bias[fr * 4 + 3];
#pragma unroll
    for (int i = 0; i < 4; i++) {
        int n = node0 + nr * 4 + i;
        if (n < N) {
            float4 v;
            v.x = acc[i][0] + b0; v.y = acc[i][1] + b1;
            v.z = acc[i][2] + b2; v.w = acc[i][3] + b3;
            if (act == 2) {
                v.x = tanhf(v.x); v.y = tanhf(v.y);
                v.z = tanhf(v.z); v.w = tanhf(v.w);
            }
            *(float4*)&out[(size_t)n * 64 + fr * 4] = v;
        }
    }
}

// ---------------- final: emb = h@W_last + b; log_softmax -----------------
__global__ void final_kernel(const float* __restrict__ h, const float* __restrict__ W,
                             const float* __restrict__ b, float* __restrict__ out,
                             int N, int out_size) {
    __shared__ float Ws[64 * 40];
    __shared__ float bs[40];
    int tid = threadIdx.x;
    for (int i = tid; i < 64 * 40; i += 256) Ws[i] = W[i];
    if (tid < 40) bs[tid] = b[tid];
    __syncthreads();

    int n = blockIdx.x * 256 + tid;
    if (n >= N) return;

    float acc[40];
#pragma unroll
    for (int c = 0; c < 40; c++) acc[c] = bs[c];
    const float* hr = h + (size_t)n * 64;
#pragma unroll 4
    for (int k = 0; k < 64; k++) {
        float hv = __ldg(&hr[k]);
#pragma unroll
        for (int c = 0; c < 40; c++) acc[c] += hv * Ws[k * 40 + c];
    }
    float mx = acc[0];
#pragma unroll
    for (int c = 1; c < 40; c++) mx = fmaxf(mx, acc[c]);
    float sum = 0.f;
#pragma unroll
    for (int c = 0; c < 40; c++) sum += expf(acc[c] - mx);
    float lse = mx + logf(sum);

    size_t base = (size_t)n * 40;
    size_t base2 = (size_t)N * 40 + base;
#pragma unroll
    for (int c = 0; c < 40; c++) {
        if (base + c < (size_t)out_size) out[base + c] = acc[c];
        if (base2 + c < (size_t)out_size) out[base2 + c] = acc[c] - lse;
    }
}

// ---------------- launch ----------------
extern "C" void kernel_launch(void* const* d_in, const int* in_sizes, int n_in,
                              void* d_out, int out_size) {
    const float* x_h    = (const float*)d_in[0];
    const float* pos    = (const float*)d_in[1];
    const int*   ei     = (const int*)  d_in[2];
    const float* W_pos  = (const float*)d_in[3];
    const float* b_pos  = (const float*)d_in[4];
    const float* W_init = (const float*)d_in[5];
    const float* b_init = (const float*)d_in[6];
    const float* W_l    = (const float*)d_in[7];
    const float* W_r    = (const float*)d_in[8];
    const float* b_conv = (const float*)d_in[9];
    const float* W_last = (const float*)d_in[10];
    const float* b_last = (const float*)d_in[11];

    int N = in_sizes[0] / 128;
    int E = in_sizes[2] / 2;

    float *hyp, *h0, *h1, *zbuf;
    __half* ybuf;
    int *rowptr, *cnt, *epos, *adj;
    cudaGetSymbolAddress((void**)&hyp,    g_hyp);
    cudaGetSymbolAddress((void**)&h0,     g_h0);
    cudaGetSymbolAddress((void**)&h1,     g_h1);
    cudaGetSymbolAddress((void**)&ybuf,   g_yh);
    cudaGetSymbolAddress((void**)&zbuf,   g_z);
    cudaGetSymbolAddress((void**)&rowptr, g_rowptr);
    cudaGetSymbolAddress((void**)&cnt,    g_cnt);
    cudaGetSymbolAddress((void**)&epos,   g_epos);
    cudaGetSymbolAddress((void**)&adj,    g_adj);

    const int* src = ei;
    const int* dst = ei + E;

    // host-side resources, created once; identical launch sequence every call
    static cudaStream_t s1 = nullptr, s2 = nullptr;
    static cudaEvent_t ev_fork = nullptr, ev_pos = nullptr, ev_join = nullptr;
    if (!s1) {
        cudaStreamCreateWithFlags(&s1, cudaStreamNonBlocking);
        cudaStreamCreateWithFlags(&s2, cudaStreamNonBlocking);
        cudaEventCreateWithFlags(&ev_fork, cudaEventDisableTiming);
        cudaEventCreateWithFlags(&ev_pos,  cudaEventDisableTiming);
        cudaEventCreateWithFlags(&ev_join, cudaEventDisableTiming);
    }

    // ---- fork: CSR on s1, pos on s2, dense pipeline on default stream ----
    cudaEventRecord(ev_fork, 0);
    cudaStreamWaitEvent(s1, ev_fork, 0);
    cudaStreamWaitEvent(s2, ev_fork, 0);

    cudaMemsetAsync(cnt, 0, (size_t)NMAX * sizeof(int), s1);
    count_kernel<<<(E + 255) / 256, 256, 0, s1>>>(dst, cnt, epos, E);
    scan_kernel <<<1, 1024, 0, s1>>>(cnt, rowptr, N);
    fill_kernel <<<(E + 255) / 256, 256, 0, s1>>>(src, dst, rowptr, epos, adj, E);
    cudaEventRecord(ev_join, s1);

    pos_kernel<<<(N + 7) / 8, 256, 0, s2>>>(pos, W_pos, b_pos, hyp, N);
    cudaEventRecord(ev_pos, s2);

    int gb64 = (N + 63) / 64;
    // h0 = x_h @ W_init + b_init  (runs concurrently with s1/s2)
    gemm_n64<<<gb64, 256>>>(x_h, 128, W_init, b_init, h0, N, 0);
    // layer 0 dual GEMM (needs hyp from s2)
    cudaStreamWaitEvent(0, ev_pos, 0);
    gemm_dual_mma<<<gb64, 256>>>(h0, W_l, W_r, b_conv, hyp, ybuf, zbuf, N);

    // ---- join: CSR must be ready before first aggregation ----
    cudaStreamWaitEvent(0, ev_join, 0);

    agg_epi<<<(N + 7) / 8, 256>>>(ybuf, zbuf, h1, rowptr, adj, N, 1);

    float* hc = h1;
    float* hn = h0;
    for (int l = 1; l < 3; l++) {
        const float* Wl = W_l + (size_t)l * 64 * 64;
        const float* Wr = W_r + (size_t)l * 64 * 64;
        const float* bc = b_conv + (size_t)l * 64;
        const float* av = (l < 2) ? hyp : nullptr;
        int act = (l < 2) ? 1 : 0;
        gemm_dual_mma<<<gb64, 256>>>(hc, Wl, Wr, bc, av, ybuf, zbuf, N);
        agg_epi<<<(N + 7) / 8, 256>>>(ybuf, zbuf, hn, rowptr, adj, N, act);
        float* t = hc; hc = hn; hn = t;
    }

    final_kernel<<<(N + 255) / 256, 256>>>(hc, W_last, b_last, (float*)d_out, N, out_size);
}